// round 14
// baseline (speedup 1.0000x reference)
#include <cuda_runtime.h>
#include <mma.h>
#include <cstdint>

using namespace nvcuda;

#define BB 8
#define DD 512
#define KK 32
#define NN 16384

// 16 MB scratch for soft-assign matrix A[b][n][k] (tf32-rounded by K1)
__device__ float A_buf[(size_t)BB * NN * KK];

__device__ __forceinline__ void cp_async16(void* smem_dst, const void* gmem_src) {
    uint32_t s = (uint32_t)__cvta_generic_to_shared(smem_dst);
    asm volatile("cp.async.cg.shared.global [%0], [%1], 16;\n" :: "r"(s), "l"(gmem_src));
}
__device__ __forceinline__ void cp_commit() {
    asm volatile("cp.async.commit_group;\n" ::: "memory");
}
template<int N>
__device__ __forceinline__ void cp_wait() {
    asm volatile("cp.async.wait_group %0;\n" :: "n"(N) : "memory");
}

// ============================================================================
// Kernel 1: A = softmax_k( s_k * (||x||^2 - 2 x.c_k + ||c_k||^2) )
//   (byte-identical to R10 passing version)
// ============================================================================
#define T1N   256
#define T1DC  64
#define NCH   (DD/T1DC)       // 8
#define TILES 4
#define X1LD 264
#define X1F  (T1DC*X1LD)
#define C1LD 516
#define C1F  (KK*C1LD)
#define AS1LD 36
#define SM1_FLOATS (2*X1F + C1F + 64)
#define SM1_BYTES  (SM1_FLOATS*4)

__global__ __launch_bounds__(512, 1)
void k1_assign(const float* __restrict__ X,
               const float* __restrict__ CW,
               const float* __restrict__ scale)
{
    extern __shared__ float sm[];
    float* Xs0 = sm;
    float* Xs1 = Xs0 + X1F;
    float* Cs  = Xs1 + X1F;
    float* c2s = Cs + C1F;
    float* scs = c2s + 32;
    float* As  = Xs0;
    float* As2 = Xs1;
    float* x2p = Xs1 + 9216;

    const int t = threadIdx.x;
    const int w = t >> 5;
    const int b = blockIdx.y;
    const int tile_base = blockIdx.x * TILES;
    const float* Xb = X + (size_t)b * DD * NN;

    const int j  = t & 63;
    const int dr = t >> 6;
    const int nc = w & 7, half = w >> 3;

    float4 R[8];
    {
        const float* g = Xb + (size_t)dr * NN + tile_base * T1N + j * 4;
        #pragma unroll
        for (int r = 0; r < 8; ++r)
            R[r] = *(const float4*)(g + (size_t)(r * 8) * NN);
    }

    for (int i = t; i < KK * DD; i += 512) {
        int k = i >> 9, d = i & 511;
        Cs[k * C1LD + d] = wmma::__float_to_tf32(CW[i]);
    }
    if (t < 32) scs[t] = scale[t];
    __syncthreads();
    if (t < 32) {
        float s = 0.f;
        #pragma unroll 8
        for (int d = 0; d < DD; ++d) { float v = Cs[t * C1LD + d]; s += v * v; }
        c2s[t] = s;
    }

    wmma::fragment<wmma::accumulator, 16, 16, 8, float> p00, p01, p10, p11;
    wmma::fill_fragment(p00, 0.f); wmma::fill_fragment(p01, 0.f);
    wmma::fill_fragment(p10, 0.f); wmma::fill_fragment(p11, 0.f);
    float xa = 0.f, xb2 = 0.f, xc = 0.f, xd2 = 0.f;

    for (int u = 0; u < TILES * NCH; ++u) {
        const int c = u & 7;
        float* Xt = (u & 1) ? Xs1 : Xs0;

        #pragma unroll
        for (int r = 0; r < 8; ++r) {
            float4 v = R[r];
            xa += v.x * v.x; xb2 += v.y * v.y; xc += v.z * v.z; xd2 += v.w * v.w;
            *(float4*)&Xt[(r * 8 + dr) * X1LD + j * 4] = v;
        }
        if (u + 1 < TILES * NCH) {
            const int un = u + 1, tn = un >> 3, cn = un & 7;
            const float* g = Xb + (size_t)(cn * T1DC + dr) * NN
                           + (size_t)(tile_base + tn) * T1N + j * 4;
            #pragma unroll
            for (int r = 0; r < 8; ++r)
                R[r] = *(const float4*)(g + (size_t)(r * 8) * NN);
        }
        __syncthreads();

        #pragma unroll
        for (int ds4 = 0; ds4 < 4; ++ds4) {
            const int dl = half * 32 + ds4 * 8;
            const int dg = c * T1DC + dl;
            wmma::fragment<wmma::matrix_a, 16, 16, 8, wmma::precision::tf32, wmma::col_major> a0, a1;
            wmma::fragment<wmma::matrix_b, 16, 16, 8, wmma::precision::tf32, wmma::col_major> b0, b1;
            wmma::load_matrix_sync(a0, Xt + dl * X1LD + nc * 32,      X1LD);
            wmma::load_matrix_sync(a1, Xt + dl * X1LD + nc * 32 + 16, X1LD);
            wmma::load_matrix_sync(b0, Cs + dg,              C1LD);
            wmma::load_matrix_sync(b1, Cs + 16 * C1LD + dg,  C1LD);
            wmma::mma_sync(p00, a0, b0, p00);
            wmma::mma_sync(p01, a0, b1, p01);
            wmma::mma_sync(p10, a1, b0, p10);
            wmma::mma_sync(p11, a1, b1, p11);
        }

        if (c == NCH - 1) {
            const int tile = u >> 3;
            const int n0 = (tile_base + tile) * T1N;
            __syncthreads();

            *(float4*)&x2p[dr * X1LD + j * 4] = make_float4(xa, xb2, xc, xd2);
            float* dst = half ? As2 : As;
            wmma::store_matrix_sync(dst + (nc * 32) * AS1LD,           p00, AS1LD, wmma::mem_row_major);
            wmma::store_matrix_sync(dst + (nc * 32) * AS1LD + 16,      p01, AS1LD, wmma::mem_row_major);
            wmma::store_matrix_sync(dst + (nc * 32 + 16) * AS1LD,      p10, AS1LD, wmma::mem_row_major);
            wmma::store_matrix_sync(dst + (nc * 32 + 16) * AS1LD + 16, p11, AS1LD, wmma::mem_row_major);
            __syncthreads();

            {
                const int n = t >> 1, h = t & 1, ks = h * 16;
                float x2n = 0.f;
                #pragma unroll
                for (int r = 0; r < 8; ++r) x2n += x2p[r * X1LD + n];
                float sl[16];
                float m = -1e30f;
                #pragma unroll
                for (int jj = 0; jj < 16; ++jj) {
                    int k = ks + jj;
                    float xck = As[n * AS1LD + k] + As2[n * AS1LD + k];
                    float v = scs[k] * (x2n - 2.f * xck + c2s[k]);
                    sl[jj] = v; m = fmaxf(m, v);
                }
                m = fmaxf(m, __shfl_xor_sync(0xffffffffu, m, 1));
                float ssum = 0.f;
                #pragma unroll
                for (int jj = 0; jj < 16; ++jj) { sl[jj] = __expf(sl[jj] - m); ssum += sl[jj]; }
                ssum += __shfl_xor_sync(0xffffffffu, ssum, 1);
                const float inv = 1.0f / ssum;
                float4 o[4];
                #pragma unroll
                for (int jj = 0; jj < 16; ++jj)
                    ((float*)o)[jj] = wmma::__float_to_tf32(sl[jj] * inv);
                float4* dstA = (float4*)&A_buf[((size_t)b * NN + n0 + n) * KK + ks];
                dstA[0] = o[0]; dstA[1] = o[1]; dstA[2] = o[2]; dstA[3] = o[3];
            }
            __syncthreads();

            wmma::fill_fragment(p00, 0.f); wmma::fill_fragment(p01, 0.f);
            wmma::fill_fragment(p10, 0.f); wmma::fill_fragment(p11, 0.f);
            xa = xb2 = xc = xd2 = 0.f;
        }
    }
}

// ============================================================================
// Kernel 2 (wide-burst, resident A): E = A^T X - S c
//   grid (32, 8), 256 threads. A-block [512n x 32k] resident (pitch 40, ==8).
//   X streamed as [64d x 128n] tiles (pitch 132, ==4): 512B contiguous rows.
//   Loop: 8 d-chunks x 4 n-subtiles, double-buffered cp.async.
//   Warp (khalf, dsub) -> D tile [16k x 16d]; 2 interleaved accumulators.
//   Per-d-chunk dump folds -S_k*c[k,d]; S precomputed from resident A.
// ============================================================================
#define CH2   512
#define T2N   128
#define DC2   64
#define NDC   (DD/DC2)         // 8
#define NSB   (CH2/T2N)        // 4
#define ITER2 (NDC*NSB)        // 32
#define ALD2  40               // == 8 (mod 32): conflict-free matrix_a
#define ABF   (CH2*ALD2)       // 20480 floats (80 KB)
#define XLD2  132              // == 4 (mod 32): conflict-free matrix_b
#define XTF   (DC2*XLD2)       // 8448 floats (33 KB) per buffer
#define SCLD  20
#define SCF   (8*2*16*SCLD)    // 5120 floats
#define SM2_FLOATS (ABF + 2*XTF + SCF + 64)
#define SM2_BYTES  (SM2_FLOATS*4)   // 170,240 B

__global__ __launch_bounds__(256, 1)
void k2_aggregate(const float* __restrict__ X,
                  const float* __restrict__ CW,
                  float* __restrict__ out)
{
    extern __shared__ float sm[];
    float* Ablk = sm;                   // [512][40]
    float* Xs0  = Ablk + ABF;           // [64][132]
    float* Xs1  = Xs0 + XTF;
    float* scr  = Xs1 + XTF;            // [8 warps][2][16][20]
    float* Ssm  = scr + SCF;            // [32]

    const int t = threadIdx.x;
    const int w = t >> 5;               // 0..7
    const int lane = t & 31;
    const int b = blockIdx.y;
    const int nbase = blockIdx.x * CH2;
    const float* Xb = X + (size_t)b * DD * NN;
    const float* Ab = A_buf + (size_t)b * NN * KK;
    float* op = out + (size_t)b * KK * DD;

    const int khalf = w >> 2;           // k in [khalf*16, +16)
    const int dsub  = w & 3;            // d-sub of 16 within the d-chunk

    // X staging map: jx = n-quad (0..31) -> 512B contiguous per d-row
    const int jx  = t & 31;
    const int dxr = t >> 5;             // 0..7

    auto stage = [&](int u) {
        const int dc = u >> 2, sub = u & 3;
        float* xd = (u & 1) ? Xs1 : Xs0;
        const float* g = Xb + (size_t)(dc * DC2) * NN + nbase + sub * T2N + jx * 4;
        #pragma unroll
        for (int r = 0; r < 8; ++r) {
            int dl = r * 8 + dxr;
            cp_async16(&xd[dl * XLD2 + jx * 4], g + (size_t)dl * NN);
        }
        cp_commit();
    };

    if (t < 32) Ssm[t] = 0.f;

    // ---- prologue: A-block (one group) + X tiles 0,1 ----
    #pragma unroll
    for (int i = 0; i < 16; ++i) {
        int idx = t + i * 256;          // 4096 quads total (512 rows x 8)
        int row = idx >> 3, q = idx & 7;
        cp_async16(&Ablk[row * ALD2 + q * 4], Ab + (size_t)(nbase + row) * KK + q * 4);
    }
    cp_commit();
    stage(0);
    stage(1);

    // ---- S_k from resident A (overlaps X tile loads in flight) ----
    cp_wait<2>();                        // A group done; X tiles still pending
    __syncthreads();
    {
        float acc = 0.f;                 // warp w sums rows [w*64, +64), lane=k
        #pragma unroll 8
        for (int n = 0; n < 64; ++n) acc += Ablk[(w * 64 + n) * ALD2 + lane];
        atomicAdd(&Ssm[lane], acc);      // ordered before mainloop's first sync
    }

    wmma::fragment<wmma::accumulator, 16, 16, 8, float> e0, e1;
    wmma::fill_fragment(e0, 0.f);
    wmma::fill_fragment(e1, 0.f);

    for (int u = 0; u < ITER2; ++u) {
        if (u + 1 < ITER2) cp_wait<1>(); else cp_wait<0>();
        __syncthreads();
        float* Xt = (u & 1) ? Xs1 : Xs0;
        const int sub = u & 3;

        // 16 n-steps; alternate accumulators to halve the serial HMMA chain
        #pragma unroll
        for (int st = 0; st < 16; st += 2) {
            wmma::fragment<wmma::matrix_a, 16, 16, 8, wmma::precision::tf32, wmma::col_major> a0, a1;
            wmma::fragment<wmma::matrix_b, 16, 16, 8, wmma::precision::tf32, wmma::col_major> b0, b1;
            wmma::load_matrix_sync(a0, Ablk + (sub * T2N + st * 8) * ALD2 + khalf * 16, ALD2);
            wmma::load_matrix_sync(b0, Xt + (dsub * 16) * XLD2 + st * 8, XLD2);
            wmma::load_matrix_sync(a1, Ablk + (sub * T2N + (st + 1) * 8) * ALD2 + khalf * 16, ALD2);
            wmma::load_matrix_sync(b1, Xt + (dsub * 16) * XLD2 + (st + 1) * 8, XLD2);
            wmma::mma_sync(e0, a0, b0, e0);
            wmma::mma_sync(e1, a1, b1, e1);
        }
        __syncthreads();                 // buffer u free
        if (u + 2 < ITER2) stage(u + 2);

        if (sub == NSB - 1) {
            // ---- dump this d-chunk: fold -S_k * c[k,d], atomicAdd ----
            const int dc = u >> 2;
            float* s0 = scr + w * 2 * 16 * SCLD;
            float* s1 = s0 + 16 * SCLD;
            wmma::store_matrix_sync(s0, e0, SCLD, wmma::mem_row_major);
            wmma::store_matrix_sync(s1, e1, SCLD, wmma::mem_row_major);
            __syncwarp();
            #pragma unroll
            for (int e = 0; e < 8; ++e) {
                int idx = lane + e * 32;     // 256 elements: 16k x 16d
                int i = idx >> 4, jj = idx & 15;
                int k = khalf * 16 + i;
                int d = dc * DC2 + dsub * 16 + jj;
                float v = s0[i * SCLD + jj] + s1[i * SCLD + jj]
                        - Ssm[k] * CW[k * DD + d];
                atomicAdd(&op[k * DD + d], v);
            }
            __syncwarp();
            wmma::fill_fragment(e0, 0.f);
            wmma::fill_fragment(e1, 0.f);
        }
    }
}

// ============================================================================
extern "C" void kernel_launch(void* const* d_in, const int* in_sizes, int n_in,
                              void* d_out, int out_size) {
    (void)in_sizes; (void)n_in;
    const float* X     = (const float*)d_in[0];
    const float* CW    = (const float*)d_in[1];
    const float* scale = (const float*)d_in[2];
    float* out = (float*)d_out;

    cudaFuncSetAttribute(k1_assign,    cudaFuncAttributeMaxDynamicSharedMemorySize, SM1_BYTES);
    cudaFuncSetAttribute(k2_aggregate, cudaFuncAttributeMaxDynamicSharedMemorySize, SM2_BYTES);

    cudaMemsetAsync(d_out, 0, (size_t)out_size * sizeof(float));

    dim3 g1(NN / (T1N * TILES), BB);   // 16 x 8 = 128 CTAs (persistent, 4 tiles)
    k1_assign<<<g1, 512, SM1_BYTES>>>(X, CW, scale);

    dim3 g2(NN / CH2, BB);             // 32 x 8 = 256 CTAs
    k2_aggregate<<<g2, 256, SM2_BYTES>>>(X, CW, out);
}

// round 15
// speedup vs baseline: 1.3034x; 1.3034x over previous
#include <cuda_runtime.h>
#include <mma.h>
#include <cstdint>

using namespace nvcuda;

#define BB 8
#define DD 512
#define KK 32
#define NN 16384

// 16 MB scratch for soft-assign matrix A[b][n][k] (tf32-rounded by K1)
__device__ float A_buf[(size_t)BB * NN * KK];

__device__ __forceinline__ void cp_async16(void* smem_dst, const void* gmem_src) {
    uint32_t s = (uint32_t)__cvta_generic_to_shared(smem_dst);
    asm volatile("cp.async.cg.shared.global [%0], [%1], 16;\n" :: "r"(s), "l"(gmem_src));
}
__device__ __forceinline__ void cp_commit() {
    asm volatile("cp.async.commit_group;\n" ::: "memory");
}
template<int N>
__device__ __forceinline__ void cp_wait() {
    asm volatile("cp.async.wait_group %0;\n" :: "n"(N) : "memory");
}

// ============================================================================
// Kernel 1: A = softmax_k( s_k * (||x||^2 - 2 x.c_k + ||c_k||^2) )
//   grid (16, 8), 512 threads, persistent 4 tiles of 256 pixels.
//   NEW: narrow-burst cp.async staging (4 d-rows x 128B per warp-op);
//        GEMM1 on warps 0-7 (full-d accumulators), x^2 on warps 8-15 from SMEM.
// ============================================================================
#define T1N   256
#define T1DC  64
#define NCH   (DD/T1DC)       // 8
#define TILES 4
#define NUNITS (TILES*NCH)    // 32
#define X1LD 264              // == 8 (mod 32): conflict-free matrix_a loads
#define X1F  (T1DC*X1LD)      // 16896 floats per buffer
#define C1LD 516              // == 4 (mod 32): conflict-free matrix_b loads
#define C1F  (KK*C1LD)        // 16512
#define AS1LD 36
#define SM1_FLOATS (2*X1F + C1F + 256 + 64)
#define SM1_BYTES  (SM1_FLOATS*4)    // 202,496 B

__global__ __launch_bounds__(512, 1)
void k1_assign(const float* __restrict__ X,
               const float* __restrict__ CW,
               const float* __restrict__ scale)
{
    extern __shared__ float sm[];
    float* Xs0 = sm;                  // [64][264]
    float* Xs1 = Xs0 + X1F;           // [64][264]
    float* Cs  = Xs1 + X1F;           // [32][516]
    float* x2s = Cs + C1F;            // [256]
    float* c2s = x2s + 256;           // [32]
    float* scs = c2s + 32;            // [32]
    float* As  = Xs1;                 // epilogue alias: [256][36] = 9216 < X1F

    const int t = threadIdx.x;
    const int w = t >> 5;
    const int b = blockIdx.y;
    const int tile_base = blockIdx.x * TILES;
    const float* Xb = X + (size_t)b * DD * NN;

    // narrow staging map: rr = d-row (0..63), q0 = base n-quad (0..7)
    const int rr = t >> 3;
    const int q0 = t & 7;

    auto stage = [&](int u) {
        const int tn = u >> 3, cn = u & 7;
        float* xd = (u & 1) ? Xs1 : Xs0;
        const float* g = Xb + (size_t)(cn * T1DC + rr) * NN
                       + (size_t)(tile_base + tn) * T1N;
        #pragma unroll
        for (int nb = 0; nb < 8; ++nb) {
            int col = nb * 8 + q0;             // quad 0..63 within 256n
            cp_async16(&xd[rr * X1LD + col * 4], g + col * 4);
        }
        cp_commit();
    };

    stage(0);
    stage(1);

    // one-time prologue under the first X loads
    for (int i = t; i < KK * DD; i += 512) {
        int k = i >> 9, d = i & 511;
        Cs[k * C1LD + d] = wmma::__float_to_tf32(CW[i]);
    }
    if (t < 32) scs[t] = scale[t];
    __syncthreads();
    if (t < 32) {
        float s = 0.f;
        #pragma unroll 8
        for (int d = 0; d < DD; ++d) { float v = Cs[t * C1LD + d]; s += v * v; }
        c2s[t] = s;   // consumed only after later barriers
    }

    // persistent per-tile state
    wmma::fragment<wmma::accumulator, 16, 16, 8, float> p00, p01, p10, p11;
    wmma::fill_fragment(p00, 0.f); wmma::fill_fragment(p01, 0.f);
    wmma::fill_fragment(p10, 0.f); wmma::fill_fragment(p11, 0.f);
    float x2acc = 0.f;                 // warps 8-15: column t-256

    for (int u = 0; u < NUNITS; ++u) {
        const int c = u & 7;
        if (u + 1 < NUNITS) cp_wait<1>(); else cp_wait<0>();
        __syncthreads();
        float* Xt = (u & 1) ? Xs1 : Xs0;

        if (w < 8) {
            // GEMM1: warp nc covers 32n x 32k over this chunk's full 64 d
            const int nc = w;
            #pragma unroll
            for (int ds = 0; ds < 8; ++ds) {
                const int dg = c * T1DC + ds * 8;
                wmma::fragment<wmma::matrix_a, 16, 16, 8, wmma::precision::tf32, wmma::col_major> a0, a1;
                wmma::fragment<wmma::matrix_b, 16, 16, 8, wmma::precision::tf32, wmma::col_major> b0, b1;
                wmma::load_matrix_sync(a0, Xt + ds * 8 * X1LD + nc * 32,      X1LD);
                wmma::load_matrix_sync(a1, Xt + ds * 8 * X1LD + nc * 32 + 16, X1LD);
                wmma::load_matrix_sync(b0, Cs + dg,             C1LD);
                wmma::load_matrix_sync(b1, Cs + 16 * C1LD + dg, C1LD);
                wmma::mma_sync(p00, a0, b0, p00);
                wmma::mma_sync(p01, a0, b1, p01);
                wmma::mma_sync(p10, a1, b0, p10);
                wmma::mma_sync(p11, a1, b1, p11);
            }
        } else {
            // x^2: thread owns column n = t-256; 64 conflict-free LDS rows
            const int n = t - 256;
            float acc = 0.f;
            #pragma unroll 16
            for (int r = 0; r < 64; ++r) {
                float v = Xt[r * X1LD + n];
                acc += v * v;
            }
            x2acc += acc;
        }
        __syncthreads();               // chunk u consumed everywhere

        if (c < NCH - 1) {
            if (u + 2 < NUNITS) stage(u + 2);
        } else {
            // ---- tile epilogue (u odd here, so u+1 in flight targets Xs0;
            //      As aliases Xs1 which is free until stage(u+2) below) ----
            const int tile = u >> 3;
            const int n0 = (tile_base + tile) * T1N;

            if (w < 8) {
                const int nc = w;
                wmma::store_matrix_sync(As + (nc * 32) * AS1LD,           p00, AS1LD, wmma::mem_row_major);
                wmma::store_matrix_sync(As + (nc * 32) * AS1LD + 16,      p01, AS1LD, wmma::mem_row_major);
                wmma::store_matrix_sync(As + (nc * 32 + 16) * AS1LD,      p10, AS1LD, wmma::mem_row_major);
                wmma::store_matrix_sync(As + (nc * 32 + 16) * AS1LD + 16, p11, AS1LD, wmma::mem_row_major);
            } else {
                x2s[t - 256] = x2acc;
                x2acc = 0.f;
            }
            __syncthreads();

            // softmax: 2 threads per pixel, 16 k each; write tf32 A coalesced
            {
                const int n = t >> 1, h = t & 1, ks = h * 16;
                const float x2n = x2s[n];
                float sl[16];
                float m = -1e30f;
                #pragma unroll
                for (int jj = 0; jj < 16; ++jj) {
                    int k = ks + jj;
                    float v = scs[k] * (x2n - 2.f * As[n * AS1LD + k] + c2s[k]);
                    sl[jj] = v; m = fmaxf(m, v);
                }
                m = fmaxf(m, __shfl_xor_sync(0xffffffffu, m, 1));
                float ssum = 0.f;
                #pragma unroll
                for (int jj = 0; jj < 16; ++jj) { sl[jj] = __expf(sl[jj] - m); ssum += sl[jj]; }
                ssum += __shfl_xor_sync(0xffffffffu, ssum, 1);
                const float inv = 1.0f / ssum;
                float4 o[4];
                #pragma unroll
                for (int jj = 0; jj < 16; ++jj)
                    ((float*)o)[jj] = wmma::__float_to_tf32(sl[jj] * inv);
                float4* dstA = (float4*)&A_buf[((size_t)b * NN + n0 + n) * KK + ks];
                dstA[0] = o[0]; dstA[1] = o[1]; dstA[2] = o[2]; dstA[3] = o[3];
            }
            __syncthreads();           // As (Xs1) free again

            wmma::fill_fragment(p00, 0.f); wmma::fill_fragment(p01, 0.f);
            wmma::fill_fragment(p10, 0.f); wmma::fill_fragment(p11, 0.f);

            if (u + 2 < NUNITS) stage(u + 2);
        }
    }
}

// ============================================================================
// Kernel 2: E[b,k,d] = sum_n A[b,n,k] * X[b,d,n]  -  S_k * c[k,d]
//   VERBATIM R10 passing version (86.9 us): grid (16,8,2), 128 thr, 2 CTAs/SM,
//   narrow cp.async staging, 4 warps x 64d, no cvt anywhere.
// ============================================================================
#define T2N    32
#define CHUNK2 1024
#define NSUB2  (CHUNK2/T2N)   // 32
#define DH     256            // d per CTA
#define X2LD 36               // == 4 (mod 32)
#define X2F  (DH*X2LD)        // 9216
#define A2LD 40               // == 8 (mod 32)
#define A2F  (T2N*A2LD)       // 1280
#define ES2LD 260
#define SM2_FLOATS (2*X2F + 2*A2F + 32)
#define SM2_BYTES  (SM2_FLOATS*4)     // 84,096 B -> 2 CTAs/SM

__global__ __launch_bounds__(128, 2)
void k2_aggregate(const float* __restrict__ X,
                  const float* __restrict__ CW,
                  float* __restrict__ out)
{
    extern __shared__ float sm[];
    float* Xs0 = sm;                // [256][36]
    float* Xs1 = Xs0 + X2F;
    float* As0 = Xs1 + X2F;         // [32][40]
    float* As1 = As0 + A2F;
    float* Ssm = As1 + A2F;         // [32]
    float* Es  = sm;                // epilogue reuse: [32][260] = 8320 < 2*X2F

    const int t = threadIdx.x;
    const int w = t >> 5;           // 0..3
    const int lane = t & 31;
    const int b = blockIdx.y;
    const int z = blockIdx.z;       // d-half
    const int nbase = blockIdx.x * CHUNK2;
    const float* Xb = X + (size_t)b * DD * NN + (size_t)z * DH * NN;
    const float* Ab = A_buf + (size_t)b * NN * KK;

    const int jx = t & 7;
    const int dxr = t >> 3;         // 0..15
    const int na = t >> 2;
    const int jaq = t & 3;

    auto stage = [&](int s) {
        const int n0 = nbase + s * T2N;
        float* xd = (s & 1) ? Xs1 : Xs0;
        float* ad = (s & 1) ? As1 : As0;
        const float* gx = Xb + n0 + jx * 4;
        #pragma unroll
        for (int r = 0; r < 16; ++r) {
            int d = r * 16 + dxr;
            cp_async16(&xd[d * X2LD + jx * 4], gx + (size_t)d * NN);
        }
        const float* ga = Ab + (size_t)(n0 + na) * KK;
        cp_async16(&ad[na * A2LD + jaq * 4],       ga + jaq * 4);
        cp_async16(&ad[na * A2LD + (jaq + 4) * 4], ga + (jaq + 4) * 4);
        cp_commit();
    };

    wmma::fragment<wmma::accumulator, 16, 16, 8, float> eacc[2][4];
    #pragma unroll
    for (int kc = 0; kc < 2; ++kc)
        #pragma unroll
        for (int dt = 0; dt < 4; ++dt)
            wmma::fill_fragment(eacc[kc][dt], 0.f);

    float sreg = 0.f;   // warp 0 lane k: running S_k

    stage(0);
    stage(1);

    for (int s = 0; s < NSUB2; ++s) {
        if (s + 1 < NSUB2) cp_wait<1>(); else cp_wait<0>();
        __syncthreads();

        float* Xt = (s & 1) ? Xs1 : Xs0;
        float* At = (s & 1) ? As1 : As0;

        if (w == 0) {
            float acc = 0.f;
            #pragma unroll
            for (int n = 0; n < T2N; ++n) acc += At[n * A2LD + lane];
            sreg += acc;
        }

        #pragma unroll
        for (int ns = 0; ns < 4; ++ns) {
            wmma::fragment<wmma::matrix_a, 16, 16, 8, wmma::precision::tf32, wmma::col_major> a2[2];
            wmma::load_matrix_sync(a2[0], At + ns * 8 * A2LD,      A2LD);
            wmma::load_matrix_sync(a2[1], At + ns * 8 * A2LD + 16, A2LD);
            #pragma unroll
            for (int dt = 0; dt < 4; ++dt) {
                wmma::fragment<wmma::matrix_b, 16, 16, 8, wmma::precision::tf32, wmma::col_major> b2;
                wmma::load_matrix_sync(b2, Xt + (w * 64 + dt * 16) * X2LD + ns * 8, X2LD);
                wmma::mma_sync(eacc[0][dt], a2[0], b2, eacc[0][dt]);
                wmma::mma_sync(eacc[1][dt], a2[1], b2, eacc[1][dt]);
            }
        }
        __syncthreads();
        if (s + 2 < NSUB2) stage(s + 2);
    }

    if (w == 0) Ssm[lane] = sreg;
    #pragma unroll
    for (int kc = 0; kc < 2; ++kc)
        #pragma unroll
        for (int dt = 0; dt < 4; ++dt)
            wmma::store_matrix_sync(Es + kc * 16 * ES2LD + w * 64 + dt * 16,
                                    eacc[kc][dt], ES2LD, wmma::mem_row_major);
    __syncthreads();

    for (int i = t; i < KK * DH; i += 128) {
        int k = i >> 8, dl = i & 255;
        int dglob = z * DH + dl;
        float v = Es[k * ES2LD + dl] - Ssm[k] * CW[k * DD + dglob];
        atomicAdd(&out[(size_t)b * KK * DD + k * DD + dglob], v);
    }
}

// ============================================================================
extern "C" void kernel_launch(void* const* d_in, const int* in_sizes, int n_in,
                              void* d_out, int out_size) {
    (void)in_sizes; (void)n_in;
    const float* X     = (const float*)d_in[0];
    const float* CW    = (const float*)d_in[1];
    const float* scale = (const float*)d_in[2];
    float* out = (float*)d_out;

    cudaFuncSetAttribute(k1_assign,    cudaFuncAttributeMaxDynamicSharedMemorySize, SM1_BYTES);
    cudaFuncSetAttribute(k2_aggregate, cudaFuncAttributeMaxDynamicSharedMemorySize, SM2_BYTES);

    cudaMemsetAsync(d_out, 0, (size_t)out_size * sizeof(float));

    dim3 g1(NN / (T1N * TILES), BB);   // 16 x 8 = 128 CTAs (persistent, 4 tiles)
    k1_assign<<<g1, 512, SM1_BYTES>>>(X, CW, scale);

    dim3 g2(NN / CHUNK2, BB, 2);       // 16 x 8 x 2 = 256 CTAs (2 per SM)
    k2_aggregate<<<g2, 128, SM2_BYTES>>>(X, CW, out);
}